// round 10
// baseline (speedup 1.0000x reference)
#include <cuda_runtime.h>
#include <cuda_bf16.h>
#include <cuda_fp16.h>
#include <cuda_fp8.h>
#include <math.h>
#include <stdint.h>

// ----------------------------------------------------------------------------
// Problem constants
// ----------------------------------------------------------------------------
#define NS   16384
#define INF_ 1024
#define H_   2048
#define NC   10
#define PRIOR_VAR 100.0

#define SCALE_W   64.0f
#define SCALE_H   8.0f
#define INV_G1    (1.0f / SCALE_W)
#define INV_G2    (1.0f / (SCALE_W * SCALE_H))

// ----------------------------------------------------------------------------
// Scratch (static device globals — no allocations allowed)
// ----------------------------------------------------------------------------
__device__ unsigned char g_Xq [NS * INF_];          // 16 MB
__device__ unsigned char g_W1q[H_ * INF_];          //  2 MB
__device__ unsigned char g_W2q[H_ * H_];            //  4 MB
__device__ unsigned char g_h1q[(size_t)NS * H_];    // 32 MB
__device__ float         g_logits[NS * NC];         // 640 KB

// ----------------------------------------------------------------------------
// PTX helpers
// ----------------------------------------------------------------------------
__device__ __forceinline__ void cp16(uint32_t dst, const void* src) {
    asm volatile("cp.async.cg.shared.global [%0], [%1], 16;" :: "r"(dst), "l"(src));
}
__device__ __forceinline__ void cp_commit() {
    asm volatile("cp.async.commit_group;");
}
template<int N> __device__ __forceinline__ void cp_wait() {
    asm volatile("cp.async.wait_group %0;" :: "n"(N));
}
__device__ __forceinline__ void ldsm_x4(uint32_t* r, uint32_t addr) {
    asm volatile("ldmatrix.sync.aligned.m8n8.x4.shared.b16 {%0,%1,%2,%3}, [%4];"
                 : "=r"(r[0]), "=r"(r[1]), "=r"(r[2]), "=r"(r[3]) : "r"(addr));
}
__device__ __forceinline__ void mma_fp8_h(uint32_t* d, const uint32_t* a,
                                          const uint32_t* b) {
    asm volatile("mma.sync.aligned.m16n8k32.row.col.f16.e4m3.e4m3.f16 "
                 "{%0,%1}, {%2,%3,%4,%5}, {%6,%7}, {%0,%1};"
                 : "+r"(d[0]), "+r"(d[1])
                 : "r"(a[0]), "r"(a[1]), "r"(a[2]), "r"(a[3]),
                   "r"(b[0]), "r"(b[1]));
}
__device__ __forceinline__ unsigned char f2e4m3(float v) {
    return (unsigned char)__nv_cvt_float_to_fp8(v, __NV_SATFINITE, __NV_E4M3);
}

// ----------------------------------------------------------------------------
// FP8 GEMM (f16 accum), R6 config: CTA 256x128, BK=64B, 3 stages, 8 warps.
//   which=0: g_h1q = fp8(8 * relu(Xq @ W1q^T / 64 + b1))           K=1024
//   which=1: partial logits += relu(h1q @ W2q^T / 512 + b2) @ W3^T K=2048
// ----------------------------------------------------------------------------
#define BM 256
#define BN 128
#define BK 64
#define STAGES 3
#define ROWB 80
#define A_STG (BM * ROWB)
#define B_STG (BN * ROWB)
#define STG_BYTES (A_STG + B_STG)
#define SMEM_DYN (STAGES * STG_BYTES)  // 92160

__global__ __launch_bounds__(256, 2)
void fp8_gemm_kernel(int which, const float* __restrict__ bias,
                     const float* __restrict__ W3g, int K)
{
    extern __shared__ unsigned char smem[];
    const unsigned char* __restrict__ A = (which == 0) ? g_Xq  : g_h1q;
    const unsigned char* __restrict__ B = (which == 0) ? g_W1q : g_W2q;

    uint32_t sb;
    asm("{ .reg .u64 t; cvta.to.shared.u64 t, %1; cvt.u32.u64 %0, t; }"
        : "=r"(sb) : "l"(smem));

    const int tid  = threadIdx.x;
    const int lane = tid & 31;
    const int warp = tid >> 5;
    const int wm   = warp >> 1;
    const int wn   = warp & 1;
    const int bm   = blockIdx.y * BM;
    const int bn   = blockIdx.x * BN;

    uint32_t acc[4][8][2];
    #pragma unroll
    for (int i = 0; i < 4; i++)
        #pragma unroll
        for (int j = 0; j < 8; j++) { acc[i][j][0] = 0u; acc[i][j][1] = 0u; }

    const int KT = K / BK;

    auto load_stage = [&](int st, int kt) {
        uint32_t aB = sb + st * STG_BYTES;
        uint32_t bB = aB + A_STG;
        const unsigned char* Ap = A + (size_t)bm * K + kt * BK;
        const unsigned char* Bp = B + (size_t)bn * K + kt * BK;
        #pragma unroll
        for (int q = 0; q < 4; q++) {
            int idx = tid + q * 256;
            int r = idx >> 2, c = (idx & 3) * 16;
            cp16(aB + r * ROWB + c, Ap + (size_t)r * K + c);
        }
        #pragma unroll
        for (int q = 0; q < 2; q++) {
            int idx = tid + q * 256;
            int r = idx >> 2, c = (idx & 3) * 16;
            cp16(bB + r * ROWB + c, Bp + (size_t)r * K + c);
        }
    };

    #pragma unroll
    for (int p = 0; p < STAGES - 1; p++) { load_stage(p, p); cp_commit(); }

    const uint32_t aOffBase =
        (uint32_t)((wm * 64 + (lane & 15)) * ROWB + (lane >> 4) * 16);
    const uint32_t bOffBase =
        (uint32_t)((wn * 64 + ((lane >> 4) & 1) * 8 + (lane & 7)) * ROWB +
                   ((lane >> 3) & 1) * 16);

    for (int i = 0; i < KT; i++) {
        const int s = i % STAGES;
        cp_wait<STAGES - 2>();
        __syncthreads();
        if (i + STAGES - 1 < KT) load_stage((i + STAGES - 1) % STAGES, i + STAGES - 1);
        cp_commit();

        const uint32_t aBase = sb + s * STG_BYTES;
        const uint32_t bBase = aBase + A_STG;
        #pragma unroll
        for (int ks = 0; ks < 2; ks++) {
            uint32_t aF[4][4];
            uint32_t bF[4][4];
            #pragma unroll
            for (int mi = 0; mi < 4; mi++)
                ldsm_x4(aF[mi], aBase + ks * 32 + aOffBase + mi * 16 * ROWB);
            #pragma unroll
            for (int njp = 0; njp < 4; njp++)
                ldsm_x4(bF[njp], bBase + ks * 32 + bOffBase + njp * 16 * ROWB);
            #pragma unroll
            for (int njp = 0; njp < 4; njp++) {
                #pragma unroll
                for (int h = 0; h < 2; h++) {
                    #pragma unroll
                    for (int mi = 0; mi < 4; mi++)
                        mma_fp8_h(acc[mi][njp * 2 + h], aF[mi], &bF[njp][2 * h]);
                }
            }
        }
    }

    if (which == 0) {
        // epilogue A: dequant + bias + relu + fp8 store of h1
        #pragma unroll
        for (int mi = 0; mi < 4; mi++) {
            int row0 = bm + wm * 64 + mi * 16 + (lane >> 2);
            #pragma unroll
            for (int nj = 0; nj < 8; nj++) {
                int col = bn + wn * 64 + nj * 8 + 2 * (lane & 3);
                float bv0 = __ldg(bias + col), bv1 = __ldg(bias + col + 1);
                float2 f01 = __half22float2(*(const __half2*)&acc[mi][nj][0]);
                float2 f23 = __half22float2(*(const __half2*)&acc[mi][nj][1]);
                float v0 = fmaxf(f01.x * INV_G1 + bv0, 0.f);
                float v1 = fmaxf(f01.y * INV_G1 + bv1, 0.f);
                float v2 = fmaxf(f23.x * INV_G1 + bv0, 0.f);
                float v3 = fmaxf(f23.y * INV_G1 + bv1, 0.f);
                unsigned short p0 = (unsigned short)f2e4m3(v0 * SCALE_H) |
                                    ((unsigned short)f2e4m3(v1 * SCALE_H) << 8);
                unsigned short p1 = (unsigned short)f2e4m3(v2 * SCALE_H) |
                                    ((unsigned short)f2e4m3(v3 * SCALE_H) << 8);
                *(unsigned short*)(g_h1q + (size_t)row0 * H_ + col)       = p0;
                *(unsigned short*)(g_h1q + (size_t)(row0 + 8) * H_ + col) = p1;
            }
        }
    } else {
        // epilogue B: h2 tile (fp32 in regs) contracted against W3 slice.
        __syncthreads();                      // all LDSMs done; smem reusable
        float* sW3 = (float*)smem;            // [NC][BN]
        float* sB2 = sW3 + NC * BN;           // [BN]
        for (int i = tid; i < NC * BN; i += 256)
            sW3[i] = __ldg(W3g + (size_t)(i / BN) * H_ + bn + (i % BN));
        for (int i = tid; i < BN; i += 256)
            sB2[i] = __ldg(bias + bn + i);
        __syncthreads();

        #pragma unroll
        for (int mi = 0; mi < 4; mi++) {
            #pragma unroll
            for (int half = 0; half < 2; half++) {
                int lrow = wm * 64 + mi * 16 + (lane >> 2) + half * 8;
                float lacc[NC];
                #pragma unroll
                for (int c = 0; c < NC; c++) lacc[c] = 0.f;
                #pragma unroll
                for (int nj = 0; nj < 8; nj++) {
                    int clo = wn * 64 + nj * 8 + 2 * (lane & 3);
                    float2 f = __half22float2(*(const __half2*)&acc[mi][nj][half]);
                    float v0 = fmaxf(f.x * INV_G2 + sB2[clo], 0.f);
                    float v1 = fmaxf(f.y * INV_G2 + sB2[clo + 1], 0.f);
                    #pragma unroll
                    for (int c = 0; c < NC; c++)
                        lacc[c] += v0 * sW3[c * BN + clo] +
                                   v1 * sW3[c * BN + clo + 1];
                }
                #pragma unroll
                for (int c = 0; c < NC; c++) {
                    lacc[c] += __shfl_xor_sync(0xFFFFFFFFu, lacc[c], 1);
                    lacc[c] += __shfl_xor_sync(0xFFFFFFFFu, lacc[c], 2);
                }
                if ((lane & 3) == 0) {
                    float* dst = g_logits + (size_t)(bm + lrow) * NC;
                    #pragma unroll
                    for (int c = 0; c < NC; c++)
                        atomicAdd(dst + c, lacc[c]);
                }
            }
        }
    }
}

// ----------------------------------------------------------------------------
// Fused fp32 -> fp8 convert (with scale) + optional prior sum-of-squares.
// ----------------------------------------------------------------------------
__global__ void conv_sumsq_kernel(const float* __restrict__ in, int n,
                                  int dst, float scale, int do_sum,
                                  float* __restrict__ out)
{
    unsigned char* o = (dst == 0) ? g_Xq : (dst == 1) ? g_W1q : g_W2q;
    float s = 0.f;
    const int gsz = gridDim.x * blockDim.x;
    const int gt  = blockIdx.x * blockDim.x + threadIdx.x;
    const int n4  = n >> 2;
    for (int i = gt; i < n4; i += gsz) {
        float4 v = ((const float4*)in)[i];
        uint32_t p = (uint32_t)f2e4m3(v.x * scale)
                   | ((uint32_t)f2e4m3(v.y * scale) << 8)
                   | ((uint32_t)f2e4m3(v.z * scale) << 16)
                   | ((uint32_t)f2e4m3(v.w * scale) << 24);
        ((uint32_t*)o)[i] = p;
        s += v.x * v.x + v.y * v.y + v.z * v.z + v.w * v.w;
    }
    if (!do_sum) return;
    #pragma unroll
    for (int ofs = 16; ofs; ofs >>= 1) s += __shfl_xor_sync(0xFFFFFFFFu, s, ofs);
    __shared__ float ws[8];
    if ((threadIdx.x & 31) == 0) ws[threadIdx.x >> 5] = s;
    __syncthreads();
    if (threadIdx.x < 8) {
        float t = ws[threadIdx.x];
        #pragma unroll
        for (int ofs = 4; ofs; ofs >>= 1) t += __shfl_xor_sync(0xFFu, t, ofs);
        if (threadIdx.x == 0) atomicAdd(out, (float)(-0.5 / PRIOR_VAR) * t);
    }
}

// ----------------------------------------------------------------------------
// Fused sum-of-squares over 4 small parameter arrays (one launch).
// ----------------------------------------------------------------------------
__global__ void sumsq4_kernel(const float* __restrict__ p0, int n0,
                              const float* __restrict__ p1, int n1,
                              const float* __restrict__ p2, int n2,
                              const float* __restrict__ p3, int n3,
                              float* __restrict__ out)
{
    float s = 0.f;
    const int gsz = gridDim.x * blockDim.x;
    const int gt  = blockIdx.x * blockDim.x + threadIdx.x;
    for (int i = gt; i < n0; i += gsz) { float v = p0[i]; s += v * v; }
    for (int i = gt; i < n1; i += gsz) { float v = p1[i]; s += v * v; }
    for (int i = gt; i < n2; i += gsz) { float v = p2[i]; s += v * v; }
    for (int i = gt; i < n3; i += gsz) { float v = p3[i]; s += v * v; }
    #pragma unroll
    for (int ofs = 16; ofs; ofs >>= 1) s += __shfl_xor_sync(0xFFFFFFFFu, s, ofs);
    __shared__ float ws[8];
    if ((threadIdx.x & 31) == 0) ws[threadIdx.x >> 5] = s;
    __syncthreads();
    if (threadIdx.x < 8) {
        float t = ws[threadIdx.x];
        #pragma unroll
        for (int ofs = 4; ofs; ofs >>= 1) t += __shfl_xor_sync(0xFFu, t, ofs);
        if (threadIdx.x == 0) atomicAdd(out, (float)(-0.5 / PRIOR_VAR) * t);
    }
}

// ----------------------------------------------------------------------------
// init: out[0] = prior constant; zero the logit accumulator.
// ----------------------------------------------------------------------------
__global__ void init_kernel(float* out, float c) {
    int gt = blockIdx.x * blockDim.x + threadIdx.x;
    if (gt == 0) out[0] = c;
    for (int i = gt; i < NS * NC; i += gridDim.x * blockDim.x)
        g_logits[i] = 0.f;
}

// ----------------------------------------------------------------------------
// loss: per-row log_softmax over g_logits + b3, gather Y, sum into out.
// ----------------------------------------------------------------------------
__global__ __launch_bounds__(256)
void loss_kernel(const float* __restrict__ b3, const int* __restrict__ Y,
                 float* __restrict__ out)
{
    int r = blockIdx.x * blockDim.x + threadIdx.x;   // one row per thread
    float lg[NC];
    float m = -1e30f;
    #pragma unroll
    for (int c = 0; c < NC; c++) {
        lg[c] = g_logits[r * NC + c] + __ldg(b3 + c);
        m = fmaxf(m, lg[c]);
    }
    float se = 0.f;
    #pragma unroll
    for (int c = 0; c < NC; c++) se += expf(lg[c] - m);
    float local = lg[Y[r]] - (m + logf(se));

    #pragma unroll
    for (int ofs = 16; ofs; ofs >>= 1)
        local += __shfl_xor_sync(0xFFFFFFFFu, local, ofs);
    __shared__ float ws[8];
    if ((threadIdx.x & 31) == 0) ws[threadIdx.x >> 5] = local;
    __syncthreads();
    if (threadIdx.x < 8) {
        float t = ws[threadIdx.x];
        #pragma unroll
        for (int ofs = 4; ofs; ofs >>= 1) t += __shfl_xor_sync(0xFFu, t, ofs);
        if (threadIdx.x == 0) atomicAdd(out, t);
    }
}

// ----------------------------------------------------------------------------
// kernel_launch
// ----------------------------------------------------------------------------
extern "C" void kernel_launch(void* const* d_in, const int* in_sizes, int n_in,
                              void* d_out, int out_size)
{
    const float* X  = (const float*)d_in[0];
    const int*   Y  = (const int*)  d_in[1];
    const float* W1 = (const float*)d_in[2];
    const float* b1 = (const float*)d_in[3];
    const float* W2 = (const float*)d_in[4];
    const float* b2 = (const float*)d_in[5];
    const float* W3 = (const float*)d_in[6];
    const float* b3 = (const float*)d_in[7];
    float* out = (float*)d_out;

    cudaFuncSetAttribute(fp8_gemm_kernel,
                         cudaFuncAttributeMaxDynamicSharedMemorySize, SMEM_DYN);

    double d = 0.0;
    for (int i = 2; i < 8; i++) d += (double)in_sizes[i];
    float cterm = (float)(-0.5 * d * log(2.0 * M_PI * PRIOR_VAR));
    init_kernel<<<160, 256>>>(out, cterm);                              // 0

    auto conv_grid = [](int n) {
        int g = (n / 4 + 255) / 256;
        if (g > 4096) g = 4096;
        return g;
    };
    conv_sumsq_kernel<<<conv_grid(NS * INF_), 256>>>(X,  NS * INF_, 0, 1.0f,    0, out); // 1
    conv_sumsq_kernel<<<conv_grid(H_ * INF_), 256>>>(W1, H_ * INF_, 1, SCALE_W, 1, out); // 2
    conv_sumsq_kernel<<<conv_grid(H_ * H_),   256>>>(W2, H_ * H_,   2, SCALE_W, 1, out); // 3

    dim3 grid(H_ / BN, NS / BM);   // (16, 64)
    fp8_gemm_kernel<<<grid, 256, SMEM_DYN>>>(0, b1, W3, INF_);          // 4
    fp8_gemm_kernel<<<grid, 256, SMEM_DYN>>>(1, b2, W3, H_);            // 5

    sumsq4_kernel<<<48, 256>>>(b1, in_sizes[3], b2, in_sizes[5],
                               W3, in_sizes[6], b3, in_sizes[7], out);  // 6
    loss_kernel<<<NS / 256, 256>>>(b3, Y, out);                         // 7
}

// round 11
// speedup vs baseline: 1.5639x; 1.5639x over previous
#include <cuda_runtime.h>
#include <cuda_bf16.h>
#include <cuda_fp16.h>
#include <cuda_fp8.h>
#include <math.h>
#include <stdint.h>

// ----------------------------------------------------------------------------
// Problem constants
// ----------------------------------------------------------------------------
#define NS   16384
#define INF_ 1024
#define H_   2048
#define NC   10
#define PRIOR_VAR 100.0

#define SCALE_W   64.0f
#define SCALE_H   8.0f
#define INV_G1    (1.0f / SCALE_W)
#define INV_G2    (1.0f / (SCALE_W * SCALE_H))

// ----------------------------------------------------------------------------
// Scratch (static device globals — no allocations allowed)
// ----------------------------------------------------------------------------
__device__ unsigned char g_Xq [NS * INF_];          // 16 MB
__device__ unsigned char g_W1q[H_ * INF_];          //  2 MB
__device__ unsigned char g_W2q[H_ * H_];            //  4 MB
__device__ unsigned char g_h1q[(size_t)NS * H_];    // 32 MB
__device__ __nv_bfloat16 g_h2 [(size_t)NS * H_];    // 64 MB

// ----------------------------------------------------------------------------
// PTX helpers
// ----------------------------------------------------------------------------
__device__ __forceinline__ void cp16(uint32_t dst, const void* src) {
    asm volatile("cp.async.cg.shared.global [%0], [%1], 16;" :: "r"(dst), "l"(src));
}
__device__ __forceinline__ void cp_commit() {
    asm volatile("cp.async.commit_group;");
}
template<int N> __device__ __forceinline__ void cp_wait() {
    asm volatile("cp.async.wait_group %0;" :: "n"(N));
}
__device__ __forceinline__ void ldsm_x4(uint32_t* r, uint32_t addr) {
    asm volatile("ldmatrix.sync.aligned.m8n8.x4.shared.b16 {%0,%1,%2,%3}, [%4];"
                 : "=r"(r[0]), "=r"(r[1]), "=r"(r[2]), "=r"(r[3]) : "r"(addr));
}
__device__ __forceinline__ void mma_fp8_h(uint32_t* d, const uint32_t* a,
                                          const uint32_t* b) {
    asm volatile("mma.sync.aligned.m16n8k32.row.col.f16.e4m3.e4m3.f16 "
                 "{%0,%1}, {%2,%3,%4,%5}, {%6,%7}, {%0,%1};"
                 : "+r"(d[0]), "+r"(d[1])
                 : "r"(a[0]), "r"(a[1]), "r"(a[2]), "r"(a[3]),
                   "r"(b[0]), "r"(b[1]));
}
__device__ __forceinline__ unsigned char f2e4m3(float v) {
    return (unsigned char)__nv_cvt_float_to_fp8(v, __NV_SATFINITE, __NV_E4M3);
}

// ----------------------------------------------------------------------------
// FP8 GEMM (f16 accum) + bias + activation.  (R6 config — best known, frozen)
//   which=0: g_h1q = fp8(8 * relu(Xq @ W1q^T / 64 + b1))        K=1024
//   which=1: g_h2  = bf16(relu(h1q @ W2q^T / 512 + b2))         K=2048
// CTA 256x128, BK=64B, 3-stage cp.async, 8 warps (4m x 2n, warp tile 64x64).
// ----------------------------------------------------------------------------
#define BM 256
#define BN 128
#define BK 64
#define STAGES 3
#define ROWB 80
#define A_STG (BM * ROWB)
#define B_STG (BN * ROWB)
#define STG_BYTES (A_STG + B_STG)
#define SMEM_DYN (STAGES * STG_BYTES)  // 92160

__global__ __launch_bounds__(256, 2)
void fp8_gemm_kernel(int which, const float* __restrict__ bias, int K)
{
    extern __shared__ unsigned char smem[];
    const unsigned char* __restrict__ A = (which == 0) ? g_Xq  : g_h1q;
    const unsigned char* __restrict__ B = (which == 0) ? g_W1q : g_W2q;

    uint32_t sb;
    asm("{ .reg .u64 t; cvta.to.shared.u64 t, %1; cvt.u32.u64 %0, t; }"
        : "=r"(sb) : "l"(smem));

    const int tid  = threadIdx.x;
    const int lane = tid & 31;
    const int warp = tid >> 5;
    const int wm   = warp >> 1;
    const int wn   = warp & 1;
    const int bm   = blockIdx.y * BM;
    const int bn   = blockIdx.x * BN;

    uint32_t acc[4][8][2];
    #pragma unroll
    for (int i = 0; i < 4; i++)
        #pragma unroll
        for (int j = 0; j < 8; j++) { acc[i][j][0] = 0u; acc[i][j][1] = 0u; }

    const int KT = K / BK;

    auto load_stage = [&](int st, int kt) {
        uint32_t aB = sb + st * STG_BYTES;
        uint32_t bB = aB + A_STG;
        const unsigned char* Ap = A + (size_t)bm * K + kt * BK;
        const unsigned char* Bp = B + (size_t)bn * K + kt * BK;
        #pragma unroll
        for (int q = 0; q < 4; q++) {
            int idx = tid + q * 256;
            int r = idx >> 2, c = (idx & 3) * 16;
            cp16(aB + r * ROWB + c, Ap + (size_t)r * K + c);
        }
        #pragma unroll
        for (int q = 0; q < 2; q++) {
            int idx = tid + q * 256;
            int r = idx >> 2, c = (idx & 3) * 16;
            cp16(bB + r * ROWB + c, Bp + (size_t)r * K + c);
        }
    };

    #pragma unroll
    for (int p = 0; p < STAGES - 1; p++) { load_stage(p, p); cp_commit(); }

    const uint32_t aOffBase =
        (uint32_t)((wm * 64 + (lane & 15)) * ROWB + (lane >> 4) * 16);
    const uint32_t bOffBase =
        (uint32_t)((wn * 64 + ((lane >> 4) & 1) * 8 + (lane & 7)) * ROWB +
                   ((lane >> 3) & 1) * 16);

    for (int i = 0; i < KT; i++) {
        const int s = i % STAGES;
        cp_wait<STAGES - 2>();
        __syncthreads();
        if (i + STAGES - 1 < KT) load_stage((i + STAGES - 1) % STAGES, i + STAGES - 1);
        cp_commit();

        const uint32_t aBase = sb + s * STG_BYTES;
        const uint32_t bBase = aBase + A_STG;
        #pragma unroll
        for (int ks = 0; ks < 2; ks++) {
            uint32_t aF[4][4];
            uint32_t bF[4][4];
            #pragma unroll
            for (int mi = 0; mi < 4; mi++)
                ldsm_x4(aF[mi], aBase + ks * 32 + aOffBase + mi * 16 * ROWB);
            #pragma unroll
            for (int njp = 0; njp < 4; njp++)
                ldsm_x4(bF[njp], bBase + ks * 32 + bOffBase + njp * 16 * ROWB);
            #pragma unroll
            for (int njp = 0; njp < 4; njp++) {
                #pragma unroll
                for (int h = 0; h < 2; h++) {
                    #pragma unroll
                    for (int mi = 0; mi < 4; mi++)
                        mma_fp8_h(acc[mi][njp * 2 + h], aF[mi], &bF[njp][2 * h]);
                }
            }
        }
    }

    // epilogue
    const float inv = (which == 0) ? INV_G1 : INV_G2;
    #pragma unroll
    for (int mi = 0; mi < 4; mi++) {
        int row0 = bm + wm * 64 + mi * 16 + (lane >> 2);
        #pragma unroll
        for (int nj = 0; nj < 8; nj++) {
            int col = bn + wn * 64 + nj * 8 + 2 * (lane & 3);
            float bv0 = __ldg(bias + col), bv1 = __ldg(bias + col + 1);
            float2 f01 = __half22float2(*(const __half2*)&acc[mi][nj][0]);
            float2 f23 = __half22float2(*(const __half2*)&acc[mi][nj][1]);
            float v0 = fmaxf(f01.x * inv + bv0, 0.f);
            float v1 = fmaxf(f01.y * inv + bv1, 0.f);
            float v2 = fmaxf(f23.x * inv + bv0, 0.f);
            float v3 = fmaxf(f23.y * inv + bv1, 0.f);
            if (which == 0) {
                unsigned short p0 = (unsigned short)f2e4m3(v0 * SCALE_H) |
                                    ((unsigned short)f2e4m3(v1 * SCALE_H) << 8);
                unsigned short p1 = (unsigned short)f2e4m3(v2 * SCALE_H) |
                                    ((unsigned short)f2e4m3(v3 * SCALE_H) << 8);
                *(unsigned short*)(g_h1q + (size_t)row0 * H_ + col)       = p0;
                *(unsigned short*)(g_h1q + (size_t)(row0 + 8) * H_ + col) = p1;
            } else {
                *(__nv_bfloat162*)(g_h2 + (size_t)row0 * H_ + col) =
                    __floats2bfloat162_rn(v0, v1);
                *(__nv_bfloat162*)(g_h2 + (size_t)(row0 + 8) * H_ + col) =
                    __floats2bfloat162_rn(v2, v3);
            }
        }
    }
}

// ----------------------------------------------------------------------------
// Fused fp32 -> fp8 convert (with scale) + optional prior sum-of-squares.
// ----------------------------------------------------------------------------
__global__ void conv_sumsq_kernel(const float* __restrict__ in, int n,
                                  int dst, float scale, int do_sum,
                                  float* __restrict__ out)
{
    unsigned char* o = (dst == 0) ? g_Xq : (dst == 1) ? g_W1q : g_W2q;
    float s = 0.f;
    const int gsz = gridDim.x * blockDim.x;
    const int gt  = blockIdx.x * blockDim.x + threadIdx.x;
    const int n4  = n >> 2;
    for (int i = gt; i < n4; i += gsz) {
        float4 v = ((const float4*)in)[i];
        uint32_t p = (uint32_t)f2e4m3(v.x * scale)
                   | ((uint32_t)f2e4m3(v.y * scale) << 8)
                   | ((uint32_t)f2e4m3(v.z * scale) << 16)
                   | ((uint32_t)f2e4m3(v.w * scale) << 24);
        ((uint32_t*)o)[i] = p;
        s += v.x * v.x + v.y * v.y + v.z * v.z + v.w * v.w;
    }
    if (!do_sum) return;
    #pragma unroll
    for (int ofs = 16; ofs; ofs >>= 1) s += __shfl_xor_sync(0xFFFFFFFFu, s, ofs);
    __shared__ float ws[8];
    if ((threadIdx.x & 31) == 0) ws[threadIdx.x >> 5] = s;
    __syncthreads();
    if (threadIdx.x < 8) {
        float t = ws[threadIdx.x];
        #pragma unroll
        for (int ofs = 4; ofs; ofs >>= 1) t += __shfl_xor_sync(0xFFu, t, ofs);
        if (threadIdx.x == 0) atomicAdd(out, (float)(-0.5 / PRIOR_VAR) * t);
    }
}

// ----------------------------------------------------------------------------
// Fused sum-of-squares over 4 small parameter arrays (one launch).
// ----------------------------------------------------------------------------
__global__ void sumsq4_kernel(const float* __restrict__ p0, int n0,
                              const float* __restrict__ p1, int n1,
                              const float* __restrict__ p2, int n2,
                              const float* __restrict__ p3, int n3,
                              float* __restrict__ out)
{
    float s = 0.f;
    const int gsz = gridDim.x * blockDim.x;
    const int gt  = blockIdx.x * blockDim.x + threadIdx.x;
    for (int i = gt; i < n0; i += gsz) { float v = p0[i]; s += v * v; }
    for (int i = gt; i < n1; i += gsz) { float v = p1[i]; s += v * v; }
    for (int i = gt; i < n2; i += gsz) { float v = p2[i]; s += v * v; }
    for (int i = gt; i < n3; i += gsz) { float v = p3[i]; s += v * v; }
    #pragma unroll
    for (int ofs = 16; ofs; ofs >>= 1) s += __shfl_xor_sync(0xFFFFFFFFu, s, ofs);
    __shared__ float ws[8];
    if ((threadIdx.x & 31) == 0) ws[threadIdx.x >> 5] = s;
    __syncthreads();
    if (threadIdx.x < 8) {
        float t = ws[threadIdx.x];
        #pragma unroll
        for (int ofs = 4; ofs; ofs >>= 1) t += __shfl_xor_sync(0xFFu, t, ofs);
        if (threadIdx.x == 0) atomicAdd(out, (float)(-0.5 / PRIOR_VAR) * t);
    }
}

// ----------------------------------------------------------------------------
// Fused head: logits = h2 @ W3^T + b3; sum log_softmax(logits)[Y].
// 8-byte vectorized loads (4 bf16 per lane per step).
// ----------------------------------------------------------------------------
__global__ __launch_bounds__(256)
void loss_kernel(const float* __restrict__ W3, const float* __restrict__ b3,
                 const int* __restrict__ Y, float* __restrict__ out)
{
    __shared__ __nv_bfloat16 sW[NC * H_];
    __shared__ float sSum;
    const int tid = threadIdx.x;
    if (tid == 0) sSum = 0.f;
    for (int i = tid; i < NC * H_ / 2; i += 256) {
        float2 w2 = ((const float2*)W3)[i];
        *(__nv_bfloat162*)(sW + 2 * i) = __floats2bfloat162_rn(w2.x, w2.y);
    }
    __syncthreads();

    const int lane = tid & 31, warp = tid >> 5;
    float local = 0.f;
    #pragma unroll
    for (int rr = 0; rr < 2; rr++) {
        int row = blockIdx.x * 16 + warp * 2 + rr;
        const __nv_bfloat16* hr = g_h2 + (size_t)row * H_;
        float acc[NC];
        #pragma unroll
        for (int c = 0; c < NC; c++) acc[c] = 0.f;
        #pragma unroll 4
        for (int i = 0; i < H_ / 128; i++) {       // 16 iters, 4 bf16/lane
            int k = i * 128 + lane * 4;
            uint2 hp = *(const uint2*)(hr + k);
            float2 ha = __bfloat1622float2(*(const __nv_bfloat162*)&hp.x);
            float2 hb = __bfloat1622float2(*(const __nv_bfloat162*)&hp.y);
            #pragma unroll
            for (int c = 0; c < NC; c++) {
                uint2 wp = *(const uint2*)(sW + c * H_ + k);
                float2 wa = __bfloat1622float2(*(const __nv_bfloat162*)&wp.x);
                float2 wb = __bfloat1622float2(*(const __nv_bfloat162*)&wp.y);
                acc[c] += ha.x * wa.x + ha.y * wa.y + hb.x * wb.x + hb.y * wb.y;
            }
        }
        #pragma unroll
        for (int c = 0; c < NC; c++) {
            #pragma unroll
            for (int o = 16; o; o >>= 1)
                acc[c] += __shfl_xor_sync(0xFFFFFFFFu, acc[c], o);
        }
        if (lane == 0) {
            float lg[NC];
            float m = -1e30f;
            #pragma unroll
            for (int c = 0; c < NC; c++) {
                lg[c] = acc[c] + b3[c];
                m = fmaxf(m, lg[c]);
            }
            float se = 0.f;
            #pragma unroll
            for (int c = 0; c < NC; c++) se += expf(lg[c] - m);
            local += lg[Y[row]] - (m + logf(se));
        }
    }
    if (lane == 0) atomicAdd(&sSum, local);
    __syncthreads();
    if (tid == 0) atomicAdd(out, sSum);
}

__global__ void init_out_kernel(float* out, float c) { out[0] = c; }

// ----------------------------------------------------------------------------
// kernel_launch
// ----------------------------------------------------------------------------
extern "C" void kernel_launch(void* const* d_in, const int* in_sizes, int n_in,
                              void* d_out, int out_size)
{
    const float* X  = (const float*)d_in[0];
    const int*   Y  = (const int*)  d_in[1];
    const float* W1 = (const float*)d_in[2];
    const float* b1 = (const float*)d_in[3];
    const float* W2 = (const float*)d_in[4];
    const float* b2 = (const float*)d_in[5];
    const float* W3 = (const float*)d_in[6];
    const float* b3 = (const float*)d_in[7];
    float* out = (float*)d_out;

    cudaFuncSetAttribute(fp8_gemm_kernel,
                         cudaFuncAttributeMaxDynamicSharedMemorySize, SMEM_DYN);

    double d = 0.0;
    for (int i = 2; i < 8; i++) d += (double)in_sizes[i];
    float cterm = (float)(-0.5 * d * log(2.0 * M_PI * PRIOR_VAR));
    init_out_kernel<<<1, 1>>>(out, cterm);                              // 0

    auto conv_grid = [](int n) {
        int g = (n / 4 + 255) / 256;
        if (g > 4096) g = 4096;
        return g;
    };
    conv_sumsq_kernel<<<conv_grid(NS * INF_), 256>>>(X,  NS * INF_, 0, 1.0f,    0, out); // 1
    conv_sumsq_kernel<<<conv_grid(H_ * INF_), 256>>>(W1, H_ * INF_, 1, SCALE_W, 1, out); // 2
    conv_sumsq_kernel<<<conv_grid(H_ * H_),   256>>>(W2, H_ * H_,   2, SCALE_W, 1, out); // 3

    dim3 grid(H_ / BN, NS / BM);   // (16, 64)
    fp8_gemm_kernel<<<grid, 256, SMEM_DYN>>>(0, b1, INF_);              // 4
    fp8_gemm_kernel<<<grid, 256, SMEM_DYN>>>(1, b2, H_);                // 5

    sumsq4_kernel<<<48, 256>>>(b1, in_sizes[3], b2, in_sizes[5],
                               W3, in_sizes[6], b3, in_sizes[7], out);  // 6
    loss_kernel<<<NS / 16, 256>>>(W3, b3, Y, out);                      // 7
}